// round 5
// baseline (speedup 1.0000x reference)
#include <cuda_runtime.h>

// Problem shape
#define TT 512
#define II 10
#define HH 32
#define EE 8                 // batch elements per block (= MMA N)
#define CH 32                // timesteps per x chunk
#define NCH (TT / CH)        // 16
#define XPAD 16              // padded feature dim (K for x part)
#define ESTR (CH * XPAD + 4) // x elem stride in floats (+4: bank-conflict skew)

typedef unsigned uu;

__device__ __forceinline__ uu tf32r(float f) {
    uu u; asm("cvt.rna.tf32.f32 %0, %1;" : "=r"(u) : "f"(f)); return u;
}
__device__ __forceinline__ float tanha(float x) {
    float r; asm("tanh.approx.f32 %0, %1;" : "=f"(r) : "f"(x)); return r;
}
// D += A(16x8) * B(8x8), tf32 inputs, fp32 accum (accumulate in place)
__device__ __forceinline__ void mma8(float& d0, float& d1, float& d2, float& d3,
                                     uu a0, uu a1, uu a2, uu a3, uu b0, uu b1) {
    asm("mma.sync.aligned.m16n8k8.row.col.f32.tf32.tf32.f32 "
        "{%0,%1,%2,%3},{%4,%5,%6,%7},{%8,%9},{%0,%1,%2,%3};"
        : "+f"(d0), "+f"(d1), "+f"(d2), "+f"(d3)
        : "r"(a0), "r"(a1), "r"(a2), "r"(a3), "r"(b0), "r"(b1));
}
__device__ __forceinline__ unsigned sm32(const void* p) {
    return (unsigned)__cvta_generic_to_shared(p);
}
__device__ __forceinline__ void cp8(unsigned d, const void* s) {
    asm volatile("cp.async.ca.shared.global [%0], [%1], 8;" :: "r"(d), "l"(s));
}

// 128 threads, 8 batch elements per block.
// Warp w computes gate w (rows 32w..32w+31) for all 8 elements via tf32 MMA.
// Thread t (t = e + 8*l form) owns c/h state for (l, e) and (l+16, e).
__global__ void __launch_bounds__(128, 3) lstm_kernel(
    const float* __restrict__ x,     const float* __restrict__ h0,
    const float* __restrict__ c0,    const float* __restrict__ W_ih,
    const float* __restrict__ W_hh,  const float* __restrict__ b_ih,
    const float* __restrict__ b_hh,  const float* __restrict__ W_lin,
    const float* __restrict__ b_lin, float* __restrict__ out)
{
    __shared__ __align__(16) float x_sh[2][EE * ESTR];     // ~33 KB
    __shared__ __align__(16) uint2 h_sh[HH][EE];           // {hi,lo} tf32 pairs
    __shared__ __align__(16) float gates_sh[4][HH][EE];    // post-activation

    const int tid  = threadIdx.x;
    const int w    = tid >> 5;          // warp = gate (0=i,1=f,2=g,3=o)
    const int gid  = (tid & 31) >> 2;   // MMA groupID (0..7)
    const int tig  = tid & 3;           // MMA threadID-in-group (0..3)
    const int base = blockIdx.x * EE;

    const float s     = (w == 2) ? 1.0f : 0.5f;   // sigmoid fold scale
    const float alpha = (w == 2) ? 1.0f : 0.5f;
    const float beta  = (w == 2) ? 0.0f : 0.5f;

    // ---- resident A fragments: W_hh (K=32) and W_ih (K=16 padded), hi/lo split ----
    uu ah_hi[2][4][4], ah_lo[2][4][4];   // [m-tile][k-chunk][a-reg]
    uu ax_hi[2][2][4], ax_lo[2][2][4];
    float bv[2][2];                      // bias per (m-tile, row-half)
    #pragma unroll
    for (int mt = 0; mt < 2; mt++) {
        #pragma unroll
        for (int rg = 0; rg < 4; rg++) {
            int row = 32 * w + 16 * mt + 8 * (rg & 1) + gid;
            #pragma unroll
            for (int kc = 0; kc < 4; kc++) {
                int col = 8 * kc + 4 * (rg >> 1) + tig;
                float v = W_hh[row * HH + col] * s;
                uu hi = tf32r(v);
                ah_hi[mt][kc][rg] = hi;
                ah_lo[mt][kc][rg] = __float_as_uint(v - __uint_as_float(hi));
            }
            #pragma unroll
            for (int kc = 0; kc < 2; kc++) {
                int j = 8 * kc + 4 * (rg >> 1) + tig;
                float v = (j < II) ? W_ih[row * II + j] * s : 0.0f;
                uu hi = tf32r(v);
                ax_hi[mt][kc][rg] = hi;
                ax_lo[mt][kc][rg] = __float_as_uint(v - __uint_as_float(hi));
            }
        }
        int r0 = 32 * w + 16 * mt + gid;
        bv[mt][0] = (b_ih[r0]     + b_hh[r0])     * s;
        bv[mt][1] = (b_ih[r0 + 8] + b_hh[r0 + 8]) * s;
    }

    // ---- per-thread state: (l, e) and (l+16, e) ----
    const int e = tid & 7;
    const int l = tid >> 3;             // 0..15
    float c_a = c0[(base + e) * HH + l];
    float c_b = c0[(base + e) * HH + l + 16];
    float h_a = h0[(base + e) * HH + l];
    float h_b = h0[(base + e) * HH + l + 16];
    const float wl0 = W_lin[l];
    const float wl1 = W_lin[l + 16];
    {
        uu p0 = tf32r(h_a), p1 = tf32r(h_b);
        h_sh[l][e]      = make_uint2(p0, __float_as_uint(h_a - __uint_as_float(p0)));
        h_sh[l + 16][e] = make_uint2(p1, __float_as_uint(h_b - __uint_as_float(p1)));
    }

    // ---- x prefetch ----
    #define PREFETCH(chunk, buf)                                                  \
        do {                                                                      \
            for (int p = tid; p < EE * CH * 5; p += 128) {                        \
                int pe = p / (CH * 5);                                            \
                int r2 = p - pe * (CH * 5);                                       \
                int t  = r2 / 5;                                                  \
                int pj = r2 - t * 5;                                              \
                const float* src = x + ((size_t)(base + pe) * TT +                \
                                        (chunk) * CH + t) * II + 2 * pj;          \
                cp8(sm32(&x_sh[buf][pe * ESTR + t * XPAD + 2 * pj]), src);        \
            }                                                                     \
            asm volatile("cp.async.commit_group;");                               \
        } while (0)

    PREFETCH(0, 0);
    // zero pad columns j=10..15 in both buffers (never written by cp.async)
    for (int p = tid; p < 2 * EE * CH * 6; p += 128) {
        int bf = p / (EE * CH * 6);
        int r  = p - bf * (EE * CH * 6);
        int pe = r / (CH * 6);
        int r2 = r - pe * (CH * 6);
        int t  = r2 / 6;
        int jj = 10 + (r2 - t * 6);
        x_sh[bf][pe * ESTR + t * XPAD + jj] = 0.0f;
    }
    asm volatile("cp.async.wait_group 0;");
    __syncthreads();

    // ---- recurrence ----
    for (int cix = 0; cix < NCH; cix++) {
        if (cix + 1 < NCH) { PREFETCH(cix + 1, (cix + 1) & 1); }
        const float* xc = x_sh[cix & 1];

        for (int tt = 0; tt < CH; tt++) {
            // B fragments: h (K=32) from h_sh, x (K=16) from x_sh
            uu bhh[8], bhl[8];
            #pragma unroll
            for (int kc = 0; kc < 4; kc++) {
                uint2 u0 = h_sh[8 * kc + tig][gid];
                uint2 u1 = h_sh[8 * kc + tig + 4][gid];
                bhh[2 * kc]     = u0.x; bhl[2 * kc]     = u0.y;
                bhh[2 * kc + 1] = u1.x; bhl[2 * kc + 1] = u1.y;
            }
            const float* xe = xc + gid * ESTR + tt * XPAD;
            uu bxh[4], bxl[4];
            #pragma unroll
            for (int kc = 0; kc < 2; kc++) {
                float v0 = xe[8 * kc + tig];
                float v1 = xe[8 * kc + tig + 4];
                uu q0 = tf32r(v0), q1 = tf32r(v1);
                bxh[2 * kc]     = q0; bxl[2 * kc]     = __float_as_uint(v0 - __uint_as_float(q0));
                bxh[2 * kc + 1] = q1; bxl[2 * kc + 1] = __float_as_uint(v1 - __uint_as_float(q1));
            }

            #pragma unroll
            for (int mt = 0; mt < 2; mt++) {
                // chain A: exact hi*hi products, bias pre-loaded
                float ca0 = bv[mt][0], ca1 = bv[mt][0];
                float ca2 = bv[mt][1], ca3 = bv[mt][1];
                // chain B: compensation terms
                float cb0 = 0.f, cb1 = 0.f, cb2 = 0.f, cb3 = 0.f;

                #pragma unroll
                for (int kc = 0; kc < 4; kc++)
                    mma8(ca0, ca1, ca2, ca3,
                         ah_hi[mt][kc][0], ah_hi[mt][kc][1], ah_hi[mt][kc][2], ah_hi[mt][kc][3],
                         bhh[2 * kc], bhh[2 * kc + 1]);
                #pragma unroll
                for (int kc = 0; kc < 2; kc++)
                    mma8(ca0, ca1, ca2, ca3,
                         ax_hi[mt][kc][0], ax_hi[mt][kc][1], ax_hi[mt][kc][2], ax_hi[mt][kc][3],
                         bxh[2 * kc], bxh[2 * kc + 1]);
                #pragma unroll
                for (int kc = 0; kc < 4; kc++) {
                    mma8(cb0, cb1, cb2, cb3,
                         ah_hi[mt][kc][0], ah_hi[mt][kc][1], ah_hi[mt][kc][2], ah_hi[mt][kc][3],
                         bhl[2 * kc], bhl[2 * kc + 1]);
                    mma8(cb0, cb1, cb2, cb3,
                         ah_lo[mt][kc][0], ah_lo[mt][kc][1], ah_lo[mt][kc][2], ah_lo[mt][kc][3],
                         bhh[2 * kc], bhh[2 * kc + 1]);
                }
                #pragma unroll
                for (int kc = 0; kc < 2; kc++) {
                    mma8(cb0, cb1, cb2, cb3,
                         ax_hi[mt][kc][0], ax_hi[mt][kc][1], ax_hi[mt][kc][2], ax_hi[mt][kc][3],
                         bxl[2 * kc], bxl[2 * kc + 1]);
                    mma8(cb0, cb1, cb2, cb3,
                         ax_lo[mt][kc][0], ax_lo[mt][kc][1], ax_lo[mt][kc][2], ax_lo[mt][kc][3],
                         bxh[2 * kc], bxh[2 * kc + 1]);
                }

                float d0 = ca0 + cb0, d1 = ca1 + cb1;
                float d2 = ca2 + cb2, d3 = ca3 + cb3;
                float a0v = fmaf(alpha, tanha(d0), beta);
                float a1v = fmaf(alpha, tanha(d1), beta);
                float a2v = fmaf(alpha, tanha(d2), beta);
                float a3v = fmaf(alpha, tanha(d3), beta);
                // rows gid / gid+8 within m-tile; cols (elems) 2tig, 2tig+1
                *reinterpret_cast<float2*>(&gates_sh[w][16 * mt + gid][2 * tig]) =
                    make_float2(a0v, a1v);
                *reinterpret_cast<float2*>(&gates_sh[w][16 * mt + 8 + gid][2 * tig]) =
                    make_float2(a2v, a3v);
            }
            __syncthreads();   // gates ready; all h_sh reads done

            // elementwise update: states (l, e) and (l+16, e)
            {
                float iv = gates_sh[0][l][e],      fv = gates_sh[1][l][e];
                float gv = gates_sh[2][l][e],      ov = gates_sh[3][l][e];
                c_a = fmaf(fv, c_a, iv * gv);
                h_a = ov * tanha(c_a);
                uu p = tf32r(h_a);
                h_sh[l][e] = make_uint2(p, __float_as_uint(h_a - __uint_as_float(p)));

                float iv2 = gates_sh[0][l + 16][e], fv2 = gates_sh[1][l + 16][e];
                float gv2 = gates_sh[2][l + 16][e], ov2 = gates_sh[3][l + 16][e];
                c_b = fmaf(fv2, c_b, iv2 * gv2);
                h_b = ov2 * tanha(c_b);
                uu p2 = tf32r(h_b);
                h_sh[l + 16][e] = make_uint2(p2, __float_as_uint(h_b - __uint_as_float(p2)));
            }
            __syncthreads();   // new h visible
        }
        asm volatile("cp.async.wait_group 0;");
        __syncthreads();
    }

    // ---- final linear head ----
    float* scratch = &gates_sh[0][0][0];      // reuse as [EE][16]
    scratch[e * 16 + l] = h_a * wl0 + h_b * wl1;
    __syncthreads();
    if (tid < EE) {
        float sum = b_lin[0];
        #pragma unroll
        for (int q = 0; q < 16; q++) sum += scratch[tid * 16 + q];
        out[base + tid] = sum;
    }
}

extern "C" void kernel_launch(void* const* d_in, const int* in_sizes, int n_in,
                              void* d_out, int out_size) {
    const float* x     = (const float*)d_in[0];
    const float* h0    = (const float*)d_in[1];
    const float* c0    = (const float*)d_in[2];
    const float* W_ih  = (const float*)d_in[3];
    const float* W_hh  = (const float*)d_in[4];
    const float* b_ih  = (const float*)d_in[5];
    const float* b_hh  = (const float*)d_in[6];
    const float* W_lin = (const float*)d_in[7];
    const float* b_lin = (const float*)d_in[8];
    float* out = (float*)d_out;

    int B = in_sizes[1] / HH;   // 4096
    lstm_kernel<<<B / EE, 128>>>(x, h0, c0, W_ih, W_hh, b_ih, b_hh, W_lin, b_lin, out);
}

// round 6
// speedup vs baseline: 1.5747x; 1.5747x over previous
#include <cuda_runtime.h>

// Problem shape
#define TT 512
#define II 10
#define HH 32
#define EE 8                 // batch elements per block (= MMA N)
#define CH 32                // timesteps per x chunk
#define NCH (TT / CH)        // 16
#define XPAD 16              // padded feature dim (K for x part)
#define ESTR (CH * XPAD + 4) // x elem stride in floats (+4: bank-conflict skew)

typedef unsigned uu;

__device__ __forceinline__ uu tf32r(float f) {
    uu u; asm("cvt.rna.tf32.f32 %0, %1;" : "=r"(u) : "f"(f)); return u;
}
__device__ __forceinline__ float tanha(float x) {
    float r; asm("tanh.approx.f32 %0, %1;" : "=f"(r) : "f"(x)); return r;
}
// D += A(16x8) * B(8x8), tf32 inputs, fp32 accum (accumulate in place)
__device__ __forceinline__ void mma8(float& d0, float& d1, float& d2, float& d3,
                                     uu a0, uu a1, uu a2, uu a3, uu b0, uu b1) {
    asm("mma.sync.aligned.m16n8k8.row.col.f32.tf32.tf32.f32 "
        "{%0,%1,%2,%3},{%4,%5,%6,%7},{%8,%9},{%0,%1,%2,%3};"
        : "+f"(d0), "+f"(d1), "+f"(d2), "+f"(d3)
        : "r"(a0), "r"(a1), "r"(a2), "r"(a3), "r"(b0), "r"(b1));
}
__device__ __forceinline__ unsigned sm32(const void* p) {
    return (unsigned)__cvta_generic_to_shared(p);
}
__device__ __forceinline__ void cp8(unsigned d, const void* s) {
    asm volatile("cp.async.ca.shared.global [%0], [%1], 8;" :: "r"(d), "l"(s));
}

// 128 threads, 8 batch elements per block, 4 blocks/SM (single wave for 512 CTAs).
// Warp w computes gate w (rows 32w..32w+31) for all 8 elements via tf32 MMA.
// Weights live in registers as tf32-hi only; precision is recovered on the B side:
//   gates = W_hi * (b_hi + b_lo), where b = [h; x] split into tf32 hi/lo.
__global__ void __launch_bounds__(128, 4) lstm_kernel(
    const float* __restrict__ x,     const float* __restrict__ h0,
    const float* __restrict__ c0,    const float* __restrict__ W_ih,
    const float* __restrict__ W_hh,  const float* __restrict__ b_ih,
    const float* __restrict__ b_hh,  const float* __restrict__ W_lin,
    const float* __restrict__ b_lin, float* __restrict__ out)
{
    __shared__ __align__(16) float x_sh[2][EE * ESTR];     // ~33 KB
    __shared__ __align__(16) uint2 h_sh[HH][EE];           // {hi,lo} tf32 pairs
    __shared__ __align__(16) float gates_sh[4][HH][EE];    // post-activation

    const int tid  = threadIdx.x;
    const int w    = tid >> 5;          // warp = gate (0=i,1=f,2=g,3=o)
    const int gid  = (tid & 31) >> 2;   // MMA groupID (0..7)
    const int tig  = tid & 3;           // MMA threadID-in-group (0..3)
    const int base = blockIdx.x * EE;

    const float s     = (w == 2) ? 1.0f : 0.5f;   // sigmoid fold scale
    const float alpha = (w == 2) ? 1.0f : 0.5f;
    const float beta  = (w == 2) ? 0.0f : 0.5f;

    // ---- resident A fragments: W_hh (K=32) and W_ih (K=16 padded), tf32-hi only ----
    uu ah[2][4][4];                      // [m-tile][k-chunk][a-reg]
    uu ax[2][2][4];
    float bv[2][2];                      // bias per (m-tile, row-half)
    #pragma unroll
    for (int mt = 0; mt < 2; mt++) {
        #pragma unroll
        for (int rg = 0; rg < 4; rg++) {
            int row = 32 * w + 16 * mt + 8 * (rg & 1) + gid;
            #pragma unroll
            for (int kc = 0; kc < 4; kc++) {
                int col = 8 * kc + 4 * (rg >> 1) + tig;
                ah[mt][kc][rg] = tf32r(W_hh[row * HH + col] * s);
            }
            #pragma unroll
            for (int kc = 0; kc < 2; kc++) {
                int j = 8 * kc + 4 * (rg >> 1) + tig;
                ax[mt][kc][rg] = tf32r((j < II) ? W_ih[row * II + j] * s : 0.0f);
            }
        }
        int r0 = 32 * w + 16 * mt + gid;
        bv[mt][0] = (b_ih[r0]     + b_hh[r0])     * s;
        bv[mt][1] = (b_ih[r0 + 8] + b_hh[r0 + 8]) * s;
    }

    // ---- per-thread state: (l, e) and (l+16, e) ----
    const int e = tid & 7;
    const int l = tid >> 3;             // 0..15
    float c_a = c0[(base + e) * HH + l];
    float c_b = c0[(base + e) * HH + l + 16];
    float h_a = h0[(base + e) * HH + l];
    float h_b = h0[(base + e) * HH + l + 16];
    const float wl0 = W_lin[l];
    const float wl1 = W_lin[l + 16];
    {
        uu p0 = tf32r(h_a), p1 = tf32r(h_b);
        h_sh[l][e]      = make_uint2(p0, __float_as_uint(h_a - __uint_as_float(p0)));
        h_sh[l + 16][e] = make_uint2(p1, __float_as_uint(h_b - __uint_as_float(p1)));
    }

    // ---- x prefetch ----
    #define PREFETCH(chunk, buf)                                                  \
        do {                                                                      \
            for (int p = tid; p < EE * CH * 5; p += 128) {                        \
                int pe = p / (CH * 5);                                            \
                int r2 = p - pe * (CH * 5);                                       \
                int t  = r2 / 5;                                                  \
                int pj = r2 - t * 5;                                              \
                const float* src = x + ((size_t)(base + pe) * TT +                \
                                        (chunk) * CH + t) * II + 2 * pj;          \
                cp8(sm32(&x_sh[buf][pe * ESTR + t * XPAD + 2 * pj]), src);        \
            }                                                                     \
            asm volatile("cp.async.commit_group;");                               \
        } while (0)

    PREFETCH(0, 0);
    // zero pad columns j=10..15 in both buffers (never written by cp.async)
    for (int p = tid; p < 2 * EE * CH * 6; p += 128) {
        int bf = p / (EE * CH * 6);
        int r  = p - bf * (EE * CH * 6);
        int pe = r / (CH * 6);
        int r2 = r - pe * (CH * 6);
        int t  = r2 / 6;
        int jj = 10 + (r2 - t * 6);
        x_sh[bf][pe * ESTR + t * XPAD + jj] = 0.0f;
    }
    asm volatile("cp.async.wait_group 0;");
    __syncthreads();

    // ---- recurrence ----
    for (int cix = 0; cix < NCH; cix++) {
        if (cix + 1 < NCH) { PREFETCH(cix + 1, (cix + 1) & 1); }
        const float* xc = x_sh[cix & 1];

        for (int tt = 0; tt < CH; tt++) {
            // B fragments: h (K=32) from h_sh, x (K=16) from x_sh, hi/lo split
            uu bhh[8], bhl[8];
            #pragma unroll
            for (int kc = 0; kc < 4; kc++) {
                uint2 u0 = h_sh[8 * kc + tig][gid];
                uint2 u1 = h_sh[8 * kc + tig + 4][gid];
                bhh[2 * kc]     = u0.x; bhl[2 * kc]     = u0.y;
                bhh[2 * kc + 1] = u1.x; bhl[2 * kc + 1] = u1.y;
            }
            const float* xe = xc + gid * ESTR + tt * XPAD;
            uu bxh[4], bxl[4];
            #pragma unroll
            for (int kc = 0; kc < 2; kc++) {
                float v0 = xe[8 * kc + tig];
                float v1 = xe[8 * kc + tig + 4];
                uu q0 = tf32r(v0), q1 = tf32r(v1);
                bxh[2 * kc]     = q0; bxl[2 * kc]     = __float_as_uint(v0 - __uint_as_float(q0));
                bxh[2 * kc + 1] = q1; bxl[2 * kc + 1] = __float_as_uint(v1 - __uint_as_float(q1));
            }

            #pragma unroll
            for (int mt = 0; mt < 2; mt++) {
                // chain A: W_hi * b_hi, bias pre-loaded (6 dependent MMAs)
                float ca0 = bv[mt][0], ca1 = bv[mt][0];
                float ca2 = bv[mt][1], ca3 = bv[mt][1];
                // chain B: W_hi * b_lo (6 dependent MMAs, independent of chain A)
                float cb0 = 0.f, cb1 = 0.f, cb2 = 0.f, cb3 = 0.f;

                #pragma unroll
                for (int kc = 0; kc < 4; kc++) {
                    mma8(ca0, ca1, ca2, ca3,
                         ah[mt][kc][0], ah[mt][kc][1], ah[mt][kc][2], ah[mt][kc][3],
                         bhh[2 * kc], bhh[2 * kc + 1]);
                    mma8(cb0, cb1, cb2, cb3,
                         ah[mt][kc][0], ah[mt][kc][1], ah[mt][kc][2], ah[mt][kc][3],
                         bhl[2 * kc], bhl[2 * kc + 1]);
                }
                #pragma unroll
                for (int kc = 0; kc < 2; kc++) {
                    mma8(ca0, ca1, ca2, ca3,
                         ax[mt][kc][0], ax[mt][kc][1], ax[mt][kc][2], ax[mt][kc][3],
                         bxh[2 * kc], bxh[2 * kc + 1]);
                    mma8(cb0, cb1, cb2, cb3,
                         ax[mt][kc][0], ax[mt][kc][1], ax[mt][kc][2], ax[mt][kc][3],
                         bxl[2 * kc], bxl[2 * kc + 1]);
                }

                float d0 = ca0 + cb0, d1 = ca1 + cb1;
                float d2 = ca2 + cb2, d3 = ca3 + cb3;
                float a0v = fmaf(alpha, tanha(d0), beta);
                float a1v = fmaf(alpha, tanha(d1), beta);
                float a2v = fmaf(alpha, tanha(d2), beta);
                float a3v = fmaf(alpha, tanha(d3), beta);
                // rows gid / gid+8 within m-tile; cols (elems) 2tig, 2tig+1
                *reinterpret_cast<float2*>(&gates_sh[w][16 * mt + gid][2 * tig]) =
                    make_float2(a0v, a1v);
                *reinterpret_cast<float2*>(&gates_sh[w][16 * mt + 8 + gid][2 * tig]) =
                    make_float2(a2v, a3v);
            }
            __syncthreads();   // gates ready; all h_sh reads done

            // elementwise update: states (l, e) and (l+16, e)
            {
                float iv = gates_sh[0][l][e],      fv = gates_sh[1][l][e];
                float gv = gates_sh[2][l][e],      ov = gates_sh[3][l][e];
                c_a = fmaf(fv, c_a, iv * gv);
                h_a = ov * tanha(c_a);
                uu p = tf32r(h_a);
                h_sh[l][e] = make_uint2(p, __float_as_uint(h_a - __uint_as_float(p)));

                float iv2 = gates_sh[0][l + 16][e], fv2 = gates_sh[1][l + 16][e];
                float gv2 = gates_sh[2][l + 16][e], ov2 = gates_sh[3][l + 16][e];
                c_b = fmaf(fv2, c_b, iv2 * gv2);
                h_b = ov2 * tanha(c_b);
                uu p2 = tf32r(h_b);
                h_sh[l + 16][e] = make_uint2(p2, __float_as_uint(h_b - __uint_as_float(p2)));
            }
            __syncthreads();   // new h visible
        }
        asm volatile("cp.async.wait_group 0;");
        __syncthreads();
    }

    // ---- final linear head ----
    float* scratch = &gates_sh[0][0][0];      // reuse as [EE][16]
    scratch[e * 16 + l] = h_a * wl0 + h_b * wl1;
    __syncthreads();
    if (tid < EE) {
        float sum = b_lin[0];
        #pragma unroll
        for (int q = 0; q < 16; q++) sum += scratch[tid * 16 + q];
        out[base + tid] = sum;
    }
}

extern "C" void kernel_launch(void* const* d_in, const int* in_sizes, int n_in,
                              void* d_out, int out_size) {
    const float* x     = (const float*)d_in[0];
    const float* h0    = (const float*)d_in[1];
    const float* c0    = (const float*)d_in[2];
    const float* W_ih  = (const float*)d_in[3];
    const float* W_hh  = (const float*)d_in[4];
    const float* b_ih  = (const float*)d_in[5];
    const float* b_hh  = (const float*)d_in[6];
    const float* W_lin = (const float*)d_in[7];
    const float* b_lin = (const float*)d_in[8];
    float* out = (float*)d_out;

    int B = in_sizes[1] / HH;   // 4096
    lstm_kernel<<<B / EE, 128>>>(x, h0, c0, W_ih, W_hh, b_ih, b_hh, W_lin, b_lin, out);
}